// round 7
// baseline (speedup 1.0000x reference)
#include <cuda_runtime.h>
#include <stddef.h>

#define T_STEPS 200
#define DS 32
#define DA 8
#define HH 128
#define NTHR 512

typedef unsigned long long u64;

// ---- smem layout (float offsets) ----
#define SLOT    16896            // staging slot size (floats)
#define OFF_DEC 33792            // dec [d][k] pad 132  (32*132 = 4224)
#define OFF_HT  38016            // h   [pair][k] f32x2, stride 268 fl (16*268 = 4288)
#define OFF_RH  42304            // r*h same layout (4288)
#define OFF_XT  46592            // gru x [pair][k<40] f32x2, stride 92 (16*92 = 1472)
#define OFF_FB  48064            // flow biases [l*512 + part*128 + n] (1024)
#define OFF_BIH 49088            // 384
#define OFF_BHH 49472            // 384
#define OFF_DB  49856            // 32
#define OFF_TV  49888            // 32
#define SMEM_FL 49920            // *4 = 199680 bytes

#define HSTR 268                 // h/rh row stride (floats), conflict-free for 8 pgs
#define XSTR 92                  // xt row stride

// ---- packed helpers ----
__device__ __forceinline__ u64 pk2(float lo, float hi) {
    u64 r; asm("mov.b64 %0,{%1,%2};" : "=l"(r) : "f"(lo), "f"(hi)); return r;
}
__device__ __forceinline__ void up2(u64 v, float& lo, float& hi) {
    asm("mov.b64 {%0,%1},%2;" : "=f"(lo), "=f"(hi) : "l"(v));
}
__device__ __forceinline__ u64 fma2(u64 a, u64 b, u64 c) {
    u64 d; asm("fma.rn.f32x2 %0,%1,%2,%3;" : "=l"(d) : "l"(a), "l"(b), "l"(c)); return d;
}
__device__ __forceinline__ u64 mul2(u64 a, u64 b) {
    u64 d; asm("mul.rn.f32x2 %0,%1,%2;" : "=l"(d) : "l"(a), "l"(b)); return d;
}
__device__ __forceinline__ u64 add2(u64 a, u64 b) {
    u64 d; asm("add.rn.f32x2 %0,%1,%2;" : "=l"(d) : "l"(a), "l"(b)); return d;
}
__device__ __forceinline__ u64 sub2(u64 a, u64 b) { float x,y,p,q; up2(a,x,y); up2(b,p,q); return pk2(x-p, y-q); }
__device__ __forceinline__ float tanha(float x) {
    float y; asm("tanh.approx.f32 %0,%1;" : "=f"(y) : "f"(x)); return y;
}
__device__ __forceinline__ float siga(float x) { return fmaf(0.5f, tanha(0.5f * x), 0.5f); }
__device__ __forceinline__ u64 tanh2(u64 v) { float a, b; up2(v, a, b); return pk2(tanha(a), tanha(b)); }

// plain (schedulable) 128-bit shared loads: two packed f32x2 values
#define LDX2(x0, x1, ptr) do { \
    const ulonglong2 _v = *reinterpret_cast<const ulonglong2*>(ptr); \
    (x0) = _v.x; (x1) = _v.y; } while (0)

__device__ __forceinline__ void cpa16(float* dst, const float* src) {
    unsigned d = (unsigned)__cvta_generic_to_shared(dst);
    asm volatile("cp.async.cg.shared.global [%0], [%1], 16;" :: "r"(d), "l"(src));
}
#define CP_COMMIT() asm volatile("cp.async.commit_group;" ::: "memory")
#define CP_WAIT0()  asm volatile("cp.async.wait_group 0;" ::: "memory")

// stage matrix for phase ph into slot ph&1
__device__ __forceinline__ void stage_matrix(int ph, float* sm, int tid,
    const float* fWr, const float* fWz, const float* fWh,
    const float* Whh, const float* Wih)
{
    float* dst = sm + (ph & 1) * SLOT;
    if (ph < 6) {
        const int l = ph / 3, w = ph % 3;
        const float* src = (w == 0 ? fWr : (w == 1 ? fWz : fWh)) + (size_t)l * 129 * 128;
        for (int i = tid; i < 4128; i += NTHR) cpa16(dst + i * 4, src + i * 4);
    } else if (ph < 9) {
        const float* src = Whh + (size_t)(ph - 6) * 128 * 128;
        for (int i = tid; i < 4096; i += NTHR) {
            int r = i >> 5, c = i & 31;
            cpa16(dst + r * 132 + c * 4, src + r * 128 + c * 4);
        }
    } else {
        for (int i = tid; i < 3840; i += NTHR) {
            int r = i / 10, c = i - r * 10;
            cpa16(dst + r * 44 + c * 4, Wih + r * 40 + c * 4);
        }
    }
}

// flow pass: weights [k][n], cols n0,n0+1; pairs pg, pg+8 (xb pre-offset by pg)
__device__ __forceinline__ void pass_flow(const float* sW, const float* xb, int n0, u64 acc[4])
{
#pragma unroll 2
    for (int k = 0; k < 128; k += 4) {
        const float2 w0 = *(const float2*)&sW[(k+0)*128 + n0];
        const float2 w1 = *(const float2*)&sW[(k+1)*128 + n0];
        const float2 w2 = *(const float2*)&sW[(k+2)*128 + n0];
        const float2 w3 = *(const float2*)&sW[(k+3)*128 + n0];
        const u64 a0 = pk2(w0.x,w0.x), b0 = pk2(w0.y,w0.y);
        const u64 a1 = pk2(w1.x,w1.x), b1 = pk2(w1.y,w1.y);
        const u64 a2 = pk2(w2.x,w2.x), b2 = pk2(w2.y,w2.y);
        const u64 a3 = pk2(w3.x,w3.x), b3 = pk2(w3.y,w3.y);
#pragma unroll
        for (int i = 0; i < 2; i++) {
            u64 x0,x1,x2,x3;
            LDX2(x0,x1, xb + i*(8*HSTR) + k*2);
            LDX2(x2,x3, xb + i*(8*HSTR) + k*2 + 4);
            acc[2*i+0] = fma2(x0,a0,acc[2*i+0]); acc[2*i+1] = fma2(x0,b0,acc[2*i+1]);
            acc[2*i+0] = fma2(x1,a1,acc[2*i+0]); acc[2*i+1] = fma2(x1,b1,acc[2*i+1]);
            acc[2*i+0] = fma2(x2,a2,acc[2*i+0]); acc[2*i+1] = fma2(x2,b2,acc[2*i+1]);
            acc[2*i+0] = fma2(x3,a3,acc[2*i+0]); acc[2*i+1] = fma2(x3,b3,acc[2*i+1]);
        }
    }
}

// gh pass: weights [n][k] pad 132, split cols n0s, n0s+64
__device__ __forceinline__ void pass_gh(const float* sW, const float* xb, int n0s, u64 acc[4])
{
#pragma unroll 2
    for (int k = 0; k < 128; k += 4) {
        const float4 wA = *(const float4*)&sW[n0s*132 + k];
        const float4 wB = *(const float4*)&sW[(n0s+64)*132 + k];
        const u64 a0 = pk2(wA.x,wA.x), a1 = pk2(wA.y,wA.y), a2 = pk2(wA.z,wA.z), a3 = pk2(wA.w,wA.w);
        const u64 b0 = pk2(wB.x,wB.x), b1 = pk2(wB.y,wB.y), b2 = pk2(wB.z,wB.z), b3 = pk2(wB.w,wB.w);
#pragma unroll
        for (int i = 0; i < 2; i++) {
            u64 x0,x1,x2,x3;
            LDX2(x0,x1, xb + i*(8*HSTR) + k*2);
            LDX2(x2,x3, xb + i*(8*HSTR) + k*2 + 4);
            acc[2*i+0] = fma2(x0,a0,acc[2*i+0]); acc[2*i+1] = fma2(x0,b0,acc[2*i+1]);
            acc[2*i+0] = fma2(x1,a1,acc[2*i+0]); acc[2*i+1] = fma2(x1,b1,acc[2*i+1]);
            acc[2*i+0] = fma2(x2,a2,acc[2*i+0]); acc[2*i+1] = fma2(x2,b2,acc[2*i+1]);
            acc[2*i+0] = fma2(x3,a3,acc[2*i+0]); acc[2*i+1] = fma2(x3,b3,acc[2*i+1]);
        }
    }
}

// gi pass: weights [n][k] pad 44 (one gate block), split cols; x = XT (K=40)
__device__ __forceinline__ void pass_gi(const float* sW, const float* xb, int n0s, u64 acc[4])
{
#pragma unroll 2
    for (int k = 0; k < 40; k += 4) {
        const float4 wA = *(const float4*)&sW[n0s*44 + k];
        const float4 wB = *(const float4*)&sW[(n0s+64)*44 + k];
        const u64 a0 = pk2(wA.x,wA.x), a1 = pk2(wA.y,wA.y), a2 = pk2(wA.z,wA.z), a3 = pk2(wA.w,wA.w);
        const u64 b0 = pk2(wB.x,wB.x), b1 = pk2(wB.y,wB.y), b2 = pk2(wB.z,wB.z), b3 = pk2(wB.w,wB.w);
#pragma unroll
        for (int i = 0; i < 2; i++) {
            u64 x0,x1,x2,x3;
            LDX2(x0,x1, xb + i*(8*XSTR) + k*2);
            LDX2(x2,x3, xb + i*(8*XSTR) + k*2 + 4);
            acc[2*i+0] = fma2(x0,a0,acc[2*i+0]); acc[2*i+1] = fma2(x0,b0,acc[2*i+1]);
            acc[2*i+0] = fma2(x1,a1,acc[2*i+0]); acc[2*i+1] = fma2(x1,b1,acc[2*i+1]);
            acc[2*i+0] = fma2(x2,a2,acc[2*i+0]); acc[2*i+1] = fma2(x2,b2,acc[2*i+1]);
            acc[2*i+0] = fma2(x3,a3,acc[2*i+0]); acc[2*i+1] = fma2(x3,b3,acc[2*i+1]);
        }
    }
}

__global__ void __launch_bounds__(NTHR, 1)
odernn_persistent(const float* __restrict__ s,   const float* __restrict__ a,
                  const float* __restrict__ t,
                  const float* __restrict__ fWr, const float* __restrict__ fbr,
                  const float* __restrict__ fWz, const float* __restrict__ fbz,
                  const float* __restrict__ fWh, const float* __restrict__ fbh,
                  const float* __restrict__ ftw,
                  const float* __restrict__ Wih, const float* __restrict__ Whh,
                  const float* __restrict__ bih, const float* __restrict__ bhh,
                  const float* __restrict__ decW, const float* __restrict__ decb,
                  float* __restrict__ outs, float* __restrict__ hids)
{
    extern __shared__ float sm[];
    const int tid  = threadIdx.x;
    const int row0 = blockIdx.x * 32;

    const int w    = tid >> 5;           // warp 0..15
    const int lane = tid & 31;
    const int pg   = lane >> 2;          // pair-group 0..7 (pairs pg, pg+8)
    const int cg   = lane & 3;           // col-group 0..3
    const int n0c  = (w * 4 + cg) * 2;   // consecutive cols (flow), 0..126
    const int n0s  = w * 4 + cg;         // split cols n0s, n0s+64 (GRU), 0..63

    const float* htb = sm + OFF_HT + pg * HSTR;
    const float* rhb = sm + OFF_RH + pg * HSTR;
    const float* xtb = sm + OFF_XT + pg * XSTR;

    // ---- one-time init ----
    for (int i = tid; i < 16 * HSTR; i += NTHR) sm[OFF_HT + i] = 0.0f;
    if (tid < 128) {
#pragma unroll
        for (int l = 0; l < 2; l++) {
            sm[OFF_FB + l * 512 +   0 + tid] = fbr[l * HH + tid];
            sm[OFF_FB + l * 512 + 128 + tid] = fbz[l * HH + tid];
            sm[OFF_FB + l * 512 + 256 + tid] = fbh[l * HH + tid];
            sm[OFF_FB + l * 512 + 384 + tid] = ftw[l * HH + tid];
        }
    }
    if (tid < 384) { sm[OFF_BIH + tid] = bih[tid]; sm[OFF_BHH + tid] = bhh[tid]; }
    if (tid < 32) sm[OFF_DB + tid] = decb[tid];
    for (int i = tid; i < 1024; i += NTHR) {       // dec [d][k] pad 132
        int r = i >> 5, c = i & 31;
        cpa16(sm + OFF_DEC + r * 132 + c * 4, decW + r * 128 + c * 4);
    }
    stage_matrix(0, sm, tid, fWr, fWz, fWh, Whh, Wih);
    CP_COMMIT();

#pragma unroll 1
    for (int ti = 0; ti < T_STEPS; ti++) {
        if (tid < 32) sm[OFF_TV + tid] = t[(size_t)(row0 + tid) * T_STEPS + ti];
        for (int i = tid; i < 32 * 40; i += NTHR) {
            const int m = i / 40, c = i - m * 40;
            const size_t row = row0 + m;
            const float v = (c < DS) ? s[(row * T_STEPS + ti) * DS + c]
                                     : a[(row * T_STEPS + ti) * DA + (c - DS)];
            sm[OFF_XT + (m >> 1) * XSTR + 2 * c + (m & 1)] = v;
        }

        u64 zz[4], tvp[2];

        // =================== flow layers ===================
#pragma unroll 1
        for (int l = 0; l < 2; l++) {
            const int phb = l * 3;
            const float* bias = sm + OFF_FB + l * 512;

            // ---- pass r ----
            CP_WAIT0(); __syncthreads();
            stage_matrix(phb + 1, sm, tid, fWr, fWz, fWh, Whh, Wih); CP_COMMIT();
            {
                const float* sW = sm + (phb & 1) * SLOT;
#pragma unroll
                for (int i = 0; i < 2; i++) {
                    const int p = pg + 8 * i;
                    tvp[i] = pk2(sm[OFF_TV + 2 * p], sm[OFF_TV + 2 * p + 1]);
                }
                u64 acc[4];
#pragma unroll
                for (int q = 0; q < 4; q++) acc[q] = 0ULL;
                pass_flow(sW, htb, n0c, acc);
                const float2 wt = *(const float2*)&sW[128 * 128 + n0c];
                const u64 wta = pk2(wt.x, wt.x), wtb = pk2(wt.y, wt.y);
                const float br0 = bias[n0c], br1 = bias[n0c + 1];
#pragma unroll
                for (int i = 0; i < 2; i++) {
                    const int p = pg + 8 * i;
                    u64 a0 = fma2(tvp[i], wta, acc[2*i+0]);
                    u64 a1 = fma2(tvp[i], wtb, acc[2*i+1]);
                    float x, y;
                    up2(a0, x, y);
                    const u64 rr0 = pk2(0.8f * siga(x + br0), 0.8f * siga(y + br0));
                    up2(a1, x, y);
                    const u64 rr1 = pk2(0.8f * siga(x + br1), 0.8f * siga(y + br1));
                    const u64 h0 = *(const u64*)&sm[OFF_HT + p * HSTR + 2 * n0c];
                    const u64 h1 = *(const u64*)&sm[OFF_HT + p * HSTR + 2 * n0c + 2];
                    *(u64*)&sm[OFF_RH + p * HSTR + 2 * n0c]     = mul2(rr0, h0);
                    *(u64*)&sm[OFF_RH + p * HSTR + 2 * n0c + 2] = mul2(rr1, h1);
                }
            }

            // ---- pass z ----
            CP_WAIT0(); __syncthreads();
            stage_matrix(phb + 2, sm, tid, fWr, fWz, fWh, Whh, Wih); CP_COMMIT();
            {
                const float* sW = sm + ((phb + 1) & 1) * SLOT;
                u64 acc[4];
#pragma unroll
                for (int q = 0; q < 4; q++) acc[q] = 0ULL;
                pass_flow(sW, htb, n0c, acc);
                const float2 wt = *(const float2*)&sW[128 * 128 + n0c];
                const u64 wta = pk2(wt.x, wt.x), wtb = pk2(wt.y, wt.y);
                const float bz0 = bias[128 + n0c], bz1 = bias[128 + n0c + 1];
#pragma unroll
                for (int i = 0; i < 2; i++) {
                    u64 a0 = fma2(tvp[i], wta, acc[2*i+0]);
                    u64 a1 = fma2(tvp[i], wtb, acc[2*i+1]);
                    float x, y;
                    up2(a0, x, y); zz[2*i+0] = pk2(0.4f * siga(x + bz0), 0.4f * siga(y + bz0));
                    up2(a1, x, y); zz[2*i+1] = pk2(0.4f * siga(x + bz1), 0.4f * siga(y + bz1));
                }
            }

            // ---- pass u + combine ----
            CP_WAIT0(); __syncthreads();
            {
                stage_matrix(phb + 3, sm, tid, fWr, fWz, fWh, Whh, Wih); CP_COMMIT();
                const float* sW = sm + ((phb + 2) & 1) * SLOT;
                u64 acc[4];
#pragma unroll
                for (int q = 0; q < 4; q++) acc[q] = 0ULL;
                pass_flow(sW, rhb, n0c, acc);
                const float2 wt = *(const float2*)&sW[128 * 128 + n0c];
                const u64 wta = pk2(wt.x, wt.x), wtb = pk2(wt.y, wt.y);
                const float bh0 = bias[256 + n0c], bh1 = bias[256 + n0c + 1];
                const float tw0 = bias[384 + n0c], tw1 = bias[384 + n0c + 1];
                const u64 bh20 = pk2(bh0, bh0), bh21 = pk2(bh1, bh1);
                const u64 tw20 = pk2(tw0, tw0), tw21 = pk2(tw1, tw1);
#pragma unroll
                for (int i = 0; i < 2; i++) {
                    const int p = pg + 8 * i;
                    const u64 u0   = tanh2(add2(fma2(tvp[i], wta, acc[2*i+0]), bh20));
                    const u64 u1   = tanh2(add2(fma2(tvp[i], wtb, acc[2*i+1]), bh21));
                    const u64 phi0 = tanh2(mul2(tw20, tvp[i]));
                    const u64 phi1 = tanh2(mul2(tw21, tvp[i]));
                    const u64 h0 = *(const u64*)&sm[OFF_HT + p * HSTR + 2 * n0c];
                    const u64 h1 = *(const u64*)&sm[OFF_HT + p * HSTR + 2 * n0c + 2];
                    const u64 hn0 = fma2(mul2(phi0, zz[2*i+0]), sub2(u0, h0), h0);
                    const u64 hn1 = fma2(mul2(phi1, zz[2*i+1]), sub2(u1, h1), h1);
                    *(u64*)&sm[OFF_HT + p * HSTR + 2 * n0c]     = hn0;
                    *(u64*)&sm[OFF_HT + p * HSTR + 2 * n0c + 2] = hn1;
                    if (l == 1) {
                        float a0lo, a0hi, a1lo, a1hi;
                        up2(hn0, a0lo, a0hi); up2(hn1, a1lo, a1hi);
                        const size_t rg = row0 + 2 * p;
                        *(float2*)&hids[(rg * T_STEPS + ti) * (size_t)HH + n0c]       = make_float2(a0lo, a1lo);
                        *(float2*)&hids[((rg + 1) * T_STEPS + ti) * (size_t)HH + n0c] = make_float2(a0hi, a1hi);
                    }
                }
            }
        }

        // =================== GRU ===================
        u64 g_r[4], g_z[4], g_in[4], g_hn[4];
        {
            const float br0 = sm[OFF_BIH + n0s] + sm[OFF_BHH + n0s];
            const float br1 = sm[OFF_BIH + n0s + 64] + sm[OFF_BHH + n0s + 64];
            const float bz0 = sm[OFF_BIH + 128 + n0s] + sm[OFF_BHH + 128 + n0s];
            const float bz1 = sm[OFF_BIH + 128 + n0s + 64] + sm[OFF_BHH + 128 + n0s + 64];
            const float bi0 = sm[OFF_BIH + 256 + n0s],      bi1 = sm[OFF_BIH + 256 + n0s + 64];
            const float bn0 = sm[OFF_BHH + 256 + n0s],      bn1 = sm[OFF_BHH + 256 + n0s + 64];
#pragma unroll
            for (int i = 0; i < 2; i++) {
                g_r[2*i+0] = pk2(br0, br0); g_r[2*i+1] = pk2(br1, br1);
                g_z[2*i+0] = pk2(bz0, bz0); g_z[2*i+1] = pk2(bz1, bz1);
                g_in[2*i+0] = pk2(bi0, bi0); g_in[2*i+1] = pk2(bi1, bi1);
                g_hn[2*i+0] = pk2(bn0, bn0); g_hn[2*i+1] = pk2(bn1, bn1);
            }
        }
        // ghr (phase 6, slot 0)
        CP_WAIT0(); __syncthreads();
        stage_matrix(7, sm, tid, fWr, fWz, fWh, Whh, Wih); CP_COMMIT();
        pass_gh(sm + 0 * SLOT, htb, n0s, g_r);
        // ghz (phase 7, slot 1)
        CP_WAIT0(); __syncthreads();
        stage_matrix(8, sm, tid, fWr, fWz, fWh, Whh, Wih); CP_COMMIT();
        pass_gh(sm + 1 * SLOT, htb, n0s, g_z);
        // ghn (phase 8, slot 0)
        CP_WAIT0(); __syncthreads();
        stage_matrix(9, sm, tid, fWr, fWz, fWh, Whh, Wih); CP_COMMIT();
        pass_gh(sm + 0 * SLOT, htb, n0s, g_hn);
        // gi (phase 9, slot 1) + combine
        CP_WAIT0(); __syncthreads();
        stage_matrix(0, sm, tid, fWr, fWz, fWh, Whh, Wih); CP_COMMIT();   // next step Wr0
        {
            const float* sW = sm + 1 * SLOT;
            pass_gi(sW,            xtb, n0s, g_r);
            pass_gi(sW + 128 * 44, xtb, n0s, g_z);
            pass_gi(sW + 256 * 44, xtb, n0s, g_in);
#pragma unroll
            for (int i = 0; i < 2; i++) {
                const int p = pg + 8 * i;
#pragma unroll
                for (int c = 0; c < 2; c++) {
                    const int n = n0s + 64 * c;
                    float rx, ry, zx, zy;
                    up2(g_r[2*i+c], rx, ry); up2(g_z[2*i+c], zx, zy);
                    const u64 r2 = pk2(siga(rx), siga(ry));
                    const u64 z2 = pk2(siga(zx), siga(zy));
                    const u64 nn2 = tanh2(fma2(r2, g_hn[2*i+c], g_in[2*i+c]));
                    const u64 h2 = *(const u64*)&sm[OFF_HT + p * HSTR + 2 * n];
                    const u64 hn2 = fma2(z2, sub2(h2, nn2), nn2);
                    *(u64*)&sm[OFF_HT + p * HSTR + 2 * n] = hn2;
                }
            }
        }
        __syncthreads();   // h_new visible for decoder

        // =================== decoder ===================
        {
            const int d = lane, grp = w;           // 16 grps x 1 pair each
            const float db = sm[OFF_DB + d];
            u64 o0 = pk2(db, db);
            const float* xa0 = sm + OFF_HT + grp * HSTR;
#pragma unroll 2
            for (int k = 0; k < 128; k += 4) {
                const float4 wv = *(const float4*)&sm[OFF_DEC + d * 132 + k];
                const u64 wa = pk2(wv.x, wv.x), wb = pk2(wv.y, wv.y);
                const u64 wc = pk2(wv.z, wv.z), wd = pk2(wv.w, wv.w);
                u64 x0, x1, x2, x3;
                LDX2(x0, x1, xa0 + k * 2);
                LDX2(x2, x3, xa0 + k * 2 + 4);
                o0 = fma2(x0, wa, o0); o0 = fma2(x1, wb, o0);
                o0 = fma2(x2, wc, o0); o0 = fma2(x3, wd, o0);
            }
            float v0, v1;
            up2(o0, v0, v1);
            const size_t r0g = row0 + 2 * grp;
            outs[((r0g + 0) * T_STEPS + ti) * (size_t)DS + d] = v0;
            outs[((r0g + 1) * T_STEPS + ti) * (size_t)DS + d] = v1;
        }
    }
}

extern "C" void kernel_launch(void* const* d_in, const int* in_sizes, int n_in,
                              void* d_out, int out_size)
{
    const float* s    = (const float*)d_in[0];
    const float* a    = (const float*)d_in[1];
    const float* t    = (const float*)d_in[2];
    const float* fWr  = (const float*)d_in[3];
    const float* fbr  = (const float*)d_in[4];
    const float* fWz  = (const float*)d_in[5];
    const float* fbz  = (const float*)d_in[6];
    const float* fWh  = (const float*)d_in[7];
    const float* fbh  = (const float*)d_in[8];
    const float* ftw  = (const float*)d_in[9];
    const float* Wih  = (const float*)d_in[10];
    const float* Whh  = (const float*)d_in[11];
    const float* bih  = (const float*)d_in[12];
    const float* bhh  = (const float*)d_in[13];
    const float* decW = (const float*)d_in[14];
    const float* decb = (const float*)d_in[15];

    float* outs = (float*)d_out;
    float* hids = outs + (size_t)4096 * T_STEPS * DS;

    const int SMEM = SMEM_FL * 4;
    cudaFuncSetAttribute(odernn_persistent, cudaFuncAttributeMaxDynamicSharedMemorySize, SMEM);
    odernn_persistent<<<128, NTHR, SMEM>>>(s, a, t, fWr, fbr, fWz, fbz, fWh, fbh, ftw,
                                           Wih, Whh, bih, bhh, decW, decb, outs, hids);
}

// round 8
// speedup vs baseline: 1.0930x; 1.0930x over previous
#include <cuda_runtime.h>
#include <stddef.h>

#define T_STEPS 200
#define DS 32
#define DA 8
#define HH 128
#define NTHR 256

typedef unsigned long long u64;

// ---- smem layout (float offsets) ----
#define SLOT    16896            // staging slot size (floats)
#define OFF_DEC 33792            // dec [d][k] pad 132  (32*132 = 4224)
#define OFF_HT  38016            // h   [pair][k] f32x2, stride 268 fl (16*268 = 4288)
#define OFF_RH  42304            // r*h same layout (4288)
#define OFF_XT  46592            // gru x [pair][k<40] f32x2, stride 92 (16*92 = 1472)
#define OFF_FB  48064            // flow biases [l*512 + part*128 + n] (1024)
#define OFF_BIH 49088            // 384
#define OFF_BHH 49472            // 384
#define OFF_DB  49856            // 32
#define OFF_TV  49888            // 32
#define SMEM_FL 49920            // *4 = 199680 bytes

#define HSTR 268                 // h/rh row stride (floats): 8 pg offsets hit all 32 banks
#define XSTR 92                  // xt row stride

// ---- packed helpers ----
__device__ __forceinline__ u64 pk2(float lo, float hi) {
    u64 r; asm("mov.b64 %0,{%1,%2};" : "=l"(r) : "f"(lo), "f"(hi)); return r;
}
__device__ __forceinline__ void up2(u64 v, float& lo, float& hi) {
    asm("mov.b64 {%0,%1},%2;" : "=f"(lo), "=f"(hi) : "l"(v));
}
__device__ __forceinline__ u64 fma2(u64 a, u64 b, u64 c) {
    u64 d; asm("fma.rn.f32x2 %0,%1,%2,%3;" : "=l"(d) : "l"(a), "l"(b), "l"(c)); return d;
}
__device__ __forceinline__ u64 mul2(u64 a, u64 b) {
    u64 d; asm("mul.rn.f32x2 %0,%1,%2;" : "=l"(d) : "l"(a), "l"(b)); return d;
}
__device__ __forceinline__ u64 add2(u64 a, u64 b) {
    u64 d; asm("add.rn.f32x2 %0,%1,%2;" : "=l"(d) : "l"(a), "l"(b)); return d;
}
__device__ __forceinline__ u64 sub2(u64 a, u64 b) { float x,y,p,q; up2(a,x,y); up2(b,p,q); return pk2(x-p, y-q); }
__device__ __forceinline__ float tanha(float x) {
    float y; asm("tanh.approx.f32 %0,%1;" : "=f"(y) : "f"(x)); return y;
}
__device__ __forceinline__ float siga(float x) { return fmaf(0.5f, tanha(0.5f * x), 0.5f); }
__device__ __forceinline__ u64 tanh2(u64 v) { float a, b; up2(v, a, b); return pk2(tanha(a), tanha(b)); }

// plain (schedulable) 128-bit shared loads: two packed f32x2 values
#define LDX2(x0, x1, ptr) do { \
    const ulonglong2 _v = *reinterpret_cast<const ulonglong2*>(ptr); \
    (x0) = _v.x; (x1) = _v.y; } while (0)

__device__ __forceinline__ void cpa16(float* dst, const float* src) {
    unsigned d = (unsigned)__cvta_generic_to_shared(dst);
    asm volatile("cp.async.cg.shared.global [%0], [%1], 16;" :: "r"(d), "l"(src));
}
#define CP_COMMIT() asm volatile("cp.async.commit_group;" ::: "memory")
#define CP_WAIT0()  asm volatile("cp.async.wait_group 0;" ::: "memory")

// stage matrix for phase ph into slot ph&1
__device__ __forceinline__ void stage_matrix(int ph, float* sm, int tid,
    const float* fWr, const float* fWz, const float* fWh,
    const float* Whh, const float* Wih)
{
    float* dst = sm + (ph & 1) * SLOT;
    if (ph < 6) {
        const int l = ph / 3, w = ph % 3;
        const float* src = (w == 0 ? fWr : (w == 1 ? fWz : fWh)) + (size_t)l * 129 * 128;
        for (int i = tid; i < 4128; i += NTHR) cpa16(dst + i * 4, src + i * 4);
    } else if (ph < 9) {
        const float* src = Whh + (size_t)(ph - 6) * 128 * 128;
        for (int i = tid; i < 4096; i += NTHR) {
            int r = i >> 5, c = i & 31;
            cpa16(dst + r * 132 + c * 4, src + r * 128 + c * 4);
        }
    } else {
        for (int i = tid; i < 3840; i += NTHR) {
            int r = i / 10, c = i - r * 10;
            cpa16(dst + r * 44 + c * 4, Wih + r * 40 + c * 4);
        }
    }
}

// flow pass: weights [k][n], 4 consecutive cols n0..n0+3; pairs pg, pg+8
// acc[4i+c] = (pair_i, col n0+c)
__device__ __forceinline__ void pass_flow(const float* sW, const float* xb, int n0, u64 acc[8])
{
#pragma unroll 2
    for (int k = 0; k < 128; k += 4) {
        const float4 w0 = *(const float4*)&sW[(k+0)*128 + n0];
        const float4 w1 = *(const float4*)&sW[(k+1)*128 + n0];
        const float4 w2 = *(const float4*)&sW[(k+2)*128 + n0];
        const float4 w3 = *(const float4*)&sW[(k+3)*128 + n0];
#pragma unroll
        for (int i = 0; i < 2; i++) {
            u64 x0,x1,x2,x3;
            LDX2(x0,x1, xb + i*(8*HSTR) + k*2);
            LDX2(x2,x3, xb + i*(8*HSTR) + k*2 + 4);
            acc[4*i+0] = fma2(x0, pk2(w0.x,w0.x), acc[4*i+0]);
            acc[4*i+1] = fma2(x0, pk2(w0.y,w0.y), acc[4*i+1]);
            acc[4*i+2] = fma2(x0, pk2(w0.z,w0.z), acc[4*i+2]);
            acc[4*i+3] = fma2(x0, pk2(w0.w,w0.w), acc[4*i+3]);
            acc[4*i+0] = fma2(x1, pk2(w1.x,w1.x), acc[4*i+0]);
            acc[4*i+1] = fma2(x1, pk2(w1.y,w1.y), acc[4*i+1]);
            acc[4*i+2] = fma2(x1, pk2(w1.z,w1.z), acc[4*i+2]);
            acc[4*i+3] = fma2(x1, pk2(w1.w,w1.w), acc[4*i+3]);
            acc[4*i+0] = fma2(x2, pk2(w2.x,w2.x), acc[4*i+0]);
            acc[4*i+1] = fma2(x2, pk2(w2.y,w2.y), acc[4*i+1]);
            acc[4*i+2] = fma2(x2, pk2(w2.z,w2.z), acc[4*i+2]);
            acc[4*i+3] = fma2(x2, pk2(w2.w,w2.w), acc[4*i+3]);
            acc[4*i+0] = fma2(x3, pk2(w3.x,w3.x), acc[4*i+0]);
            acc[4*i+1] = fma2(x3, pk2(w3.y,w3.y), acc[4*i+1]);
            acc[4*i+2] = fma2(x3, pk2(w3.z,w3.z), acc[4*i+2]);
            acc[4*i+3] = fma2(x3, pk2(w3.w,w3.w), acc[4*i+3]);
        }
    }
}

// gh pass: weights [n][k] pad 132, cols {n0s, +32, +64, +96}
__device__ __forceinline__ void pass_gh(const float* sW, const float* xb, int n0s, u64 acc[8])
{
#pragma unroll 2
    for (int k = 0; k < 128; k += 4) {
        const float4 wA = *(const float4*)&sW[(n0s +  0)*132 + k];
        const float4 wB = *(const float4*)&sW[(n0s + 32)*132 + k];
        const float4 wC = *(const float4*)&sW[(n0s + 64)*132 + k];
        const float4 wD = *(const float4*)&sW[(n0s + 96)*132 + k];
#pragma unroll
        for (int i = 0; i < 2; i++) {
            u64 x0,x1,x2,x3;
            LDX2(x0,x1, xb + i*(8*HSTR) + k*2);
            LDX2(x2,x3, xb + i*(8*HSTR) + k*2 + 4);
            acc[4*i+0] = fma2(x0, pk2(wA.x,wA.x), acc[4*i+0]);
            acc[4*i+0] = fma2(x1, pk2(wA.y,wA.y), acc[4*i+0]);
            acc[4*i+0] = fma2(x2, pk2(wA.z,wA.z), acc[4*i+0]);
            acc[4*i+0] = fma2(x3, pk2(wA.w,wA.w), acc[4*i+0]);
            acc[4*i+1] = fma2(x0, pk2(wB.x,wB.x), acc[4*i+1]);
            acc[4*i+1] = fma2(x1, pk2(wB.y,wB.y), acc[4*i+1]);
            acc[4*i+1] = fma2(x2, pk2(wB.z,wB.z), acc[4*i+1]);
            acc[4*i+1] = fma2(x3, pk2(wB.w,wB.w), acc[4*i+1]);
            acc[4*i+2] = fma2(x0, pk2(wC.x,wC.x), acc[4*i+2]);
            acc[4*i+2] = fma2(x1, pk2(wC.y,wC.y), acc[4*i+2]);
            acc[4*i+2] = fma2(x2, pk2(wC.z,wC.z), acc[4*i+2]);
            acc[4*i+2] = fma2(x3, pk2(wC.w,wC.w), acc[4*i+2]);
            acc[4*i+3] = fma2(x0, pk2(wD.x,wD.x), acc[4*i+3]);
            acc[4*i+3] = fma2(x1, pk2(wD.y,wD.y), acc[4*i+3]);
            acc[4*i+3] = fma2(x2, pk2(wD.z,wD.z), acc[4*i+3]);
            acc[4*i+3] = fma2(x3, pk2(wD.w,wD.w), acc[4*i+3]);
        }
    }
}

// gi pass: weights [n][k] pad 44 (one gate block), cols {n0s,+32,+64,+96}; x = XT (K=40)
__device__ __forceinline__ void pass_gi(const float* sW, const float* xb, int n0s, u64 acc[8])
{
#pragma unroll 2
    for (int k = 0; k < 40; k += 4) {
        const float4 wA = *(const float4*)&sW[(n0s +  0)*44 + k];
        const float4 wB = *(const float4*)&sW[(n0s + 32)*44 + k];
        const float4 wC = *(const float4*)&sW[(n0s + 64)*44 + k];
        const float4 wD = *(const float4*)&sW[(n0s + 96)*44 + k];
#pragma unroll
        for (int i = 0; i < 2; i++) {
            u64 x0,x1,x2,x3;
            LDX2(x0,x1, xb + i*(8*XSTR) + k*2);
            LDX2(x2,x3, xb + i*(8*XSTR) + k*2 + 4);
            acc[4*i+0] = fma2(x0, pk2(wA.x,wA.x), acc[4*i+0]);
            acc[4*i+0] = fma2(x1, pk2(wA.y,wA.y), acc[4*i+0]);
            acc[4*i+0] = fma2(x2, pk2(wA.z,wA.z), acc[4*i+0]);
            acc[4*i+0] = fma2(x3, pk2(wA.w,wA.w), acc[4*i+0]);
            acc[4*i+1] = fma2(x0, pk2(wB.x,wB.x), acc[4*i+1]);
            acc[4*i+1] = fma2(x1, pk2(wB.y,wB.y), acc[4*i+1]);
            acc[4*i+1] = fma2(x2, pk2(wB.z,wB.z), acc[4*i+1]);
            acc[4*i+1] = fma2(x3, pk2(wB.w,wB.w), acc[4*i+1]);
            acc[4*i+2] = fma2(x0, pk2(wC.x,wC.x), acc[4*i+2]);
            acc[4*i+2] = fma2(x1, pk2(wC.y,wC.y), acc[4*i+2]);
            acc[4*i+2] = fma2(x2, pk2(wC.z,wC.z), acc[4*i+2]);
            acc[4*i+2] = fma2(x3, pk2(wC.w,wC.w), acc[4*i+2]);
            acc[4*i+3] = fma2(x0, pk2(wD.x,wD.x), acc[4*i+3]);
            acc[4*i+3] = fma2(x1, pk2(wD.y,wD.y), acc[4*i+3]);
            acc[4*i+3] = fma2(x2, pk2(wD.z,wD.z), acc[4*i+3]);
            acc[4*i+3] = fma2(x3, pk2(wD.w,wD.w), acc[4*i+3]);
        }
    }
}

__global__ void __launch_bounds__(NTHR, 1)
odernn_persistent(const float* __restrict__ s,   const float* __restrict__ a,
                  const float* __restrict__ t,
                  const float* __restrict__ fWr, const float* __restrict__ fbr,
                  const float* __restrict__ fWz, const float* __restrict__ fbz,
                  const float* __restrict__ fWh, const float* __restrict__ fbh,
                  const float* __restrict__ ftw,
                  const float* __restrict__ Wih, const float* __restrict__ Whh,
                  const float* __restrict__ bih, const float* __restrict__ bhh,
                  const float* __restrict__ decW, const float* __restrict__ decb,
                  float* __restrict__ outs, float* __restrict__ hids)
{
    extern __shared__ float sm[];
    const int tid  = threadIdx.x;
    const int row0 = blockIdx.x * 32;

    const int w    = tid >> 5;           // warp 0..7
    const int lane = tid & 31;
    const int pg   = lane >> 2;          // pair-group 0..7 (pairs pg, pg+8)
    const int cg   = lane & 3;           // col-group 0..3
    const int n0c  = w * 16 + cg * 4;    // 4 consecutive cols (flow), 0..124
    const int n0s  = w * 4 + cg;         // GRU col base 0..31, cols {n0s,+32,+64,+96}

    const float* htb = sm + OFF_HT + pg * HSTR;
    const float* rhb = sm + OFF_RH + pg * HSTR;
    const float* xtb = sm + OFF_XT + pg * XSTR;

    // ---- one-time init ----
    for (int i = tid; i < 16 * HSTR; i += NTHR) sm[OFF_HT + i] = 0.0f;
    if (tid < 128) {
#pragma unroll
        for (int l = 0; l < 2; l++) {
            sm[OFF_FB + l * 512 +   0 + tid] = fbr[l * HH + tid];
            sm[OFF_FB + l * 512 + 128 + tid] = fbz[l * HH + tid];
            sm[OFF_FB + l * 512 + 256 + tid] = fbh[l * HH + tid];
            sm[OFF_FB + l * 512 + 384 + tid] = ftw[l * HH + tid];
        }
    }
    for (int i = tid; i < 384; i += NTHR) { sm[OFF_BIH + i] = bih[i]; sm[OFF_BHH + i] = bhh[i]; }
    if (tid < 32) sm[OFF_DB + tid] = decb[tid];
    for (int i = tid; i < 1024; i += NTHR) {       // dec [d][k] pad 132
        int r = i >> 5, c = i & 31;
        cpa16(sm + OFF_DEC + r * 132 + c * 4, decW + r * 128 + c * 4);
    }
    stage_matrix(0, sm, tid, fWr, fWz, fWh, Whh, Wih);
    CP_COMMIT();

#pragma unroll 1
    for (int ti = 0; ti < T_STEPS; ti++) {
        if (tid < 32) sm[OFF_TV + tid] = t[(size_t)(row0 + tid) * T_STEPS + ti];
        for (int i = tid; i < 32 * 40; i += NTHR) {
            const int m = i / 40, c = i - m * 40;
            const size_t row = row0 + m;
            const float v = (c < DS) ? s[(row * T_STEPS + ti) * DS + c]
                                     : a[(row * T_STEPS + ti) * DA + (c - DS)];
            sm[OFF_XT + (m >> 1) * XSTR + 2 * c + (m & 1)] = v;
        }

        u64 zz[8], tvp[2];

        // =================== flow layers ===================
#pragma unroll 1
        for (int l = 0; l < 2; l++) {
            const int phb = l * 3;
            const float* bias = sm + OFF_FB + l * 512;

            // ---- pass r ----
            CP_WAIT0(); __syncthreads();
            stage_matrix(phb + 1, sm, tid, fWr, fWz, fWh, Whh, Wih); CP_COMMIT();
            {
                const float* sW = sm + (phb & 1) * SLOT;
#pragma unroll
                for (int i = 0; i < 2; i++) {
                    const int p = pg + 8 * i;
                    tvp[i] = pk2(sm[OFF_TV + 2 * p], sm[OFF_TV + 2 * p + 1]);
                }
                u64 acc[8];
#pragma unroll
                for (int q = 0; q < 8; q++) acc[q] = 0ULL;
                pass_flow(sW, htb, n0c, acc);
                const float4 wt = *(const float4*)&sW[128 * 128 + n0c];
                const float4 br = *(const float4*)&bias[n0c];
#pragma unroll
                for (int i = 0; i < 2; i++) {
                    const int p = pg + 8 * i;
                    const ulonglong2 hA = *(const ulonglong2*)&sm[OFF_HT + p * HSTR + 2 * n0c];
                    const ulonglong2 hB = *(const ulonglong2*)&sm[OFF_HT + p * HSTR + 2 * n0c + 4];
                    float x, y;
                    ulonglong2 oA, oB;
                    up2(fma2(tvp[i], pk2(wt.x,wt.x), acc[4*i+0]), x, y);
                    oA.x = mul2(pk2(0.8f*siga(x+br.x), 0.8f*siga(y+br.x)), hA.x);
                    up2(fma2(tvp[i], pk2(wt.y,wt.y), acc[4*i+1]), x, y);
                    oA.y = mul2(pk2(0.8f*siga(x+br.y), 0.8f*siga(y+br.y)), hA.y);
                    up2(fma2(tvp[i], pk2(wt.z,wt.z), acc[4*i+2]), x, y);
                    oB.x = mul2(pk2(0.8f*siga(x+br.z), 0.8f*siga(y+br.z)), hB.x);
                    up2(fma2(tvp[i], pk2(wt.w,wt.w), acc[4*i+3]), x, y);
                    oB.y = mul2(pk2(0.8f*siga(x+br.w), 0.8f*siga(y+br.w)), hB.y);
                    *(ulonglong2*)&sm[OFF_RH + p * HSTR + 2 * n0c]     = oA;
                    *(ulonglong2*)&sm[OFF_RH + p * HSTR + 2 * n0c + 4] = oB;
                }
            }

            // ---- pass z ----
            CP_WAIT0(); __syncthreads();
            stage_matrix(phb + 2, sm, tid, fWr, fWz, fWh, Whh, Wih); CP_COMMIT();
            {
                const float* sW = sm + ((phb + 1) & 1) * SLOT;
                u64 acc[8];
#pragma unroll
                for (int q = 0; q < 8; q++) acc[q] = 0ULL;
                pass_flow(sW, htb, n0c, acc);
                const float4 wt = *(const float4*)&sW[128 * 128 + n0c];
                const float4 bz = *(const float4*)&bias[128 + n0c];
#pragma unroll
                for (int i = 0; i < 2; i++) {
                    float x, y;
                    up2(fma2(tvp[i], pk2(wt.x,wt.x), acc[4*i+0]), x, y);
                    zz[4*i+0] = pk2(0.4f*siga(x+bz.x), 0.4f*siga(y+bz.x));
                    up2(fma2(tvp[i], pk2(wt.y,wt.y), acc[4*i+1]), x, y);
                    zz[4*i+1] = pk2(0.4f*siga(x+bz.y), 0.4f*siga(y+bz.y));
                    up2(fma2(tvp[i], pk2(wt.z,wt.z), acc[4*i+2]), x, y);
                    zz[4*i+2] = pk2(0.4f*siga(x+bz.z), 0.4f*siga(y+bz.z));
                    up2(fma2(tvp[i], pk2(wt.w,wt.w), acc[4*i+3]), x, y);
                    zz[4*i+3] = pk2(0.4f*siga(x+bz.w), 0.4f*siga(y+bz.w));
                }
            }

            // ---- pass u + combine ----
            CP_WAIT0(); __syncthreads();
            {
                stage_matrix(phb + 3, sm, tid, fWr, fWz, fWh, Whh, Wih); CP_COMMIT();
                const float* sW = sm + ((phb + 2) & 1) * SLOT;
                u64 acc[8];
#pragma unroll
                for (int q = 0; q < 8; q++) acc[q] = 0ULL;
                pass_flow(sW, rhb, n0c, acc);
                const float4 wt = *(const float4*)&sW[128 * 128 + n0c];
                const float4 bh = *(const float4*)&bias[256 + n0c];
                const float4 tw = *(const float4*)&bias[384 + n0c];
#pragma unroll
                for (int i = 0; i < 2; i++) {
                    const int p = pg + 8 * i;
                    const ulonglong2 hA = *(const ulonglong2*)&sm[OFF_HT + p * HSTR + 2 * n0c];
                    const ulonglong2 hB = *(const ulonglong2*)&sm[OFF_HT + p * HSTR + 2 * n0c + 4];
                    const u64 u0 = tanh2(add2(fma2(tvp[i], pk2(wt.x,wt.x), acc[4*i+0]), pk2(bh.x,bh.x)));
                    const u64 u1 = tanh2(add2(fma2(tvp[i], pk2(wt.y,wt.y), acc[4*i+1]), pk2(bh.y,bh.y)));
                    const u64 u2 = tanh2(add2(fma2(tvp[i], pk2(wt.z,wt.z), acc[4*i+2]), pk2(bh.z,bh.z)));
                    const u64 u3 = tanh2(add2(fma2(tvp[i], pk2(wt.w,wt.w), acc[4*i+3]), pk2(bh.w,bh.w)));
                    const u64 f0 = tanh2(mul2(pk2(tw.x,tw.x), tvp[i]));
                    const u64 f1 = tanh2(mul2(pk2(tw.y,tw.y), tvp[i]));
                    const u64 f2 = tanh2(mul2(pk2(tw.z,tw.z), tvp[i]));
                    const u64 f3 = tanh2(mul2(pk2(tw.w,tw.w), tvp[i]));
                    ulonglong2 oA, oB;
                    oA.x = fma2(mul2(f0, zz[4*i+0]), sub2(u0, hA.x), hA.x);
                    oA.y = fma2(mul2(f1, zz[4*i+1]), sub2(u1, hA.y), hA.y);
                    oB.x = fma2(mul2(f2, zz[4*i+2]), sub2(u2, hB.x), hB.x);
                    oB.y = fma2(mul2(f3, zz[4*i+3]), sub2(u3, hB.y), hB.y);
                    *(ulonglong2*)&sm[OFF_HT + p * HSTR + 2 * n0c]     = oA;
                    *(ulonglong2*)&sm[OFF_HT + p * HSTR + 2 * n0c + 4] = oB;
                    if (l == 1) {
                        float l0,h0,l1,h1,l2,h2,l3,h3;
                        up2(oA.x, l0, h0); up2(oA.y, l1, h1);
                        up2(oB.x, l2, h2); up2(oB.y, l3, h3);
                        const size_t rg = row0 + 2 * p;
                        *(float4*)&hids[(rg * T_STEPS + ti) * (size_t)HH + n0c]       = make_float4(l0, l1, l2, l3);
                        *(float4*)&hids[((rg + 1) * T_STEPS + ti) * (size_t)HH + n0c] = make_float4(h0, h1, h2, h3);
                    }
                }
            }
        }

        // =================== GRU ===================
        u64 g_r[8], g_z[8], g_in[8], g_hn[8];
        {
#pragma unroll
            for (int c = 0; c < 4; c++) {
                const int n = n0s + 32 * c;
                const float br = sm[OFF_BIH + n] + sm[OFF_BHH + n];
                const float bz = sm[OFF_BIH + 128 + n] + sm[OFF_BHH + 128 + n];
                const float bi = sm[OFF_BIH + 256 + n];
                const float bn = sm[OFF_BHH + 256 + n];
#pragma unroll
                for (int i = 0; i < 2; i++) {
                    g_r[4*i+c]  = pk2(br, br);
                    g_z[4*i+c]  = pk2(bz, bz);
                    g_in[4*i+c] = pk2(bi, bi);
                    g_hn[4*i+c] = pk2(bn, bn);
                }
            }
        }
        // ghr (phase 6, slot 0)
        CP_WAIT0(); __syncthreads();
        stage_matrix(7, sm, tid, fWr, fWz, fWh, Whh, Wih); CP_COMMIT();
        pass_gh(sm + 0 * SLOT, htb, n0s, g_r);
        // ghz (phase 7, slot 1)
        CP_WAIT0(); __syncthreads();
        stage_matrix(8, sm, tid, fWr, fWz, fWh, Whh, Wih); CP_COMMIT();
        pass_gh(sm + 1 * SLOT, htb, n0s, g_z);
        // ghn (phase 8, slot 0)
        CP_WAIT0(); __syncthreads();
        stage_matrix(9, sm, tid, fWr, fWz, fWh, Whh, Wih); CP_COMMIT();
        pass_gh(sm + 0 * SLOT, htb, n0s, g_hn);
        // gi (phase 9, slot 1) + combine
        CP_WAIT0(); __syncthreads();
        stage_matrix(0, sm, tid, fWr, fWz, fWh, Whh, Wih); CP_COMMIT();   // next step Wr0
        {
            const float* sW = sm + 1 * SLOT;
            pass_gi(sW,            xtb, n0s, g_r);
            pass_gi(sW + 128 * 44, xtb, n0s, g_z);
            pass_gi(sW + 256 * 44, xtb, n0s, g_in);
#pragma unroll
            for (int i = 0; i < 2; i++) {
                const int p = pg + 8 * i;
#pragma unroll
                for (int c = 0; c < 4; c++) {
                    const int n = n0s + 32 * c;
                    float rx, ry, zx, zy;
                    up2(g_r[4*i+c], rx, ry); up2(g_z[4*i+c], zx, zy);
                    const u64 r2 = pk2(siga(rx), siga(ry));
                    const u64 z2 = pk2(siga(zx), siga(zy));
                    const u64 nn2 = tanh2(fma2(r2, g_hn[4*i+c], g_in[4*i+c]));
                    const u64 h2 = *(const u64*)&sm[OFF_HT + p * HSTR + 2 * n];
                    const u64 hn2 = fma2(z2, sub2(h2, nn2), nn2);
                    *(u64*)&sm[OFF_HT + p * HSTR + 2 * n] = hn2;
                }
            }
        }
        __syncthreads();   // h_new visible for decoder

        // =================== decoder ===================
        {
            const int d = tid & 31, grp = tid >> 5;   // 8 grps x 2 pairs
            const float db = sm[OFF_DB + d];
            u64 o0 = pk2(db, db), o1 = pk2(db, db);
            const float* xa0 = sm + OFF_HT + (2 * grp) * HSTR;
            const float* xa1 = xa0 + HSTR;
#pragma unroll 2
            for (int k = 0; k < 128; k += 4) {
                const float4 wv = *(const float4*)&sm[OFF_DEC + d * 132 + k];
                const u64 wa = pk2(wv.x, wv.x), wb = pk2(wv.y, wv.y);
                const u64 wc = pk2(wv.z, wv.z), wd = pk2(wv.w, wv.w);
                u64 x0, x1, x2, x3;
                LDX2(x0, x1, xa0 + k * 2);
                LDX2(x2, x3, xa0 + k * 2 + 4);
                o0 = fma2(x0, wa, o0); o0 = fma2(x1, wb, o0);
                o0 = fma2(x2, wc, o0); o0 = fma2(x3, wd, o0);
                LDX2(x0, x1, xa1 + k * 2);
                LDX2(x2, x3, xa1 + k * 2 + 4);
                o1 = fma2(x0, wa, o1); o1 = fma2(x1, wb, o1);
                o1 = fma2(x2, wc, o1); o1 = fma2(x3, wd, o1);
            }
            float v0, v1, v2, v3;
            up2(o0, v0, v1); up2(o1, v2, v3);
            const size_t r0g = row0 + 4 * grp;
            outs[((r0g + 0) * T_STEPS + ti) * (size_t)DS + d] = v0;
            outs[((r0g + 1) * T_STEPS + ti) * (size_t)DS + d] = v1;
            outs[((r0g + 2) * T_STEPS + ti) * (size_t)DS + d] = v2;
            outs[((r0g + 3) * T_STEPS + ti) * (size_t)DS + d] = v3;
        }
    }
}

extern "C" void kernel_launch(void* const* d_in, const int* in_sizes, int n_in,
                              void* d_out, int out_size)
{
    const float* s    = (const float*)d_in[0];
    const float* a    = (const float*)d_in[1];
    const float* t    = (const float*)d_in[2];
    const float* fWr  = (const float*)d_in[3];
    const float* fbr  = (const float*)d_in[4];
    const float* fWz  = (const float*)d_in[5];
    const float* fbz  = (const float*)d_in[6];
    const float* fWh  = (const float*)d_in[7];
    const float* fbh  = (const float*)d_in[8];
    const float* ftw  = (const float*)d_in[9];
    const float* Wih  = (const float*)d_in[10];
    const float* Whh  = (const float*)d_in[11];
    const float* bih  = (const float*)d_in[12];
    const float* bhh  = (const float*)d_in[13];
    const float* decW = (const float*)d_in[14];
    const float* decb = (const float*)d_in[15];

    float* outs = (float*)d_out;
    float* hids = outs + (size_t)4096 * T_STEPS * DS;

    const int SMEM = SMEM_FL * 4;
    cudaFuncSetAttribute(odernn_persistent, cudaFuncAttributeMaxDynamicSharedMemorySize, SMEM);
    odernn_persistent<<<128, NTHR, SMEM>>>(s, a, t, fWr, fbr, fWz, fbz, fWh, fbh, ftw,
                                           Wih, Whh, bih, bhh, decW, decb, outs, hids);
}

// round 9
// speedup vs baseline: 1.1250x; 1.0293x over previous
#include <cuda_runtime.h>
#include <stddef.h>

#define T_STEPS 200
#define DS 32
#define DA 8
#define HH 128
#define NTHR 512

typedef unsigned long long u64;

// ---- smem layout (float offsets) ----
#define SLOT    16896            // staging slot size (floats)
#define OFF_DEC 33792            // dec [d][k] pad 132  (32*132 = 4224)
#define OFF_HT  38016            // h   [pair][k] f32x2, stride 268 fl (16*268 = 4288)
#define OFF_RH  42304            // r*h same layout (4288)
#define OFF_XT  46592            // gru x [pair][k<40] f32x2, stride 92 (16*92 = 1472)
#define OFF_FB  48064            // flow biases [l*512 + part*128 + n] (1024)
#define OFF_BIH 49088            // 384
#define OFF_BHH 49472            // 384
#define OFF_DB  49856            // 32
#define OFF_TV  49888            // 32
#define OFF_SCR 49920            // split-K partial scratch: 8 * 512 floats (16KB)
#define SMEM_FL 54016            // *4 = 216064 bytes

#define HSTR 268                 // h/rh row stride (floats): 8 pg offsets hit all 32 banks
#define XSTR 92                  // xt row stride

// ---- packed helpers ----
__device__ __forceinline__ u64 pk2(float lo, float hi) {
    u64 r; asm("mov.b64 %0,{%1,%2};" : "=l"(r) : "f"(lo), "f"(hi)); return r;
}
__device__ __forceinline__ void up2(u64 v, float& lo, float& hi) {
    asm("mov.b64 {%0,%1},%2;" : "=f"(lo), "=f"(hi) : "l"(v));
}
__device__ __forceinline__ u64 fma2(u64 a, u64 b, u64 c) {
    u64 d; asm("fma.rn.f32x2 %0,%1,%2,%3;" : "=l"(d) : "l"(a), "l"(b), "l"(c)); return d;
}
__device__ __forceinline__ u64 mul2(u64 a, u64 b) {
    u64 d; asm("mul.rn.f32x2 %0,%1,%2;" : "=l"(d) : "l"(a), "l"(b)); return d;
}
__device__ __forceinline__ u64 add2(u64 a, u64 b) {
    u64 d; asm("add.rn.f32x2 %0,%1,%2;" : "=l"(d) : "l"(a), "l"(b)); return d;
}
__device__ __forceinline__ u64 sub2(u64 a, u64 b) { float x,y,p,q; up2(a,x,y); up2(b,p,q); return pk2(x-p, y-q); }
__device__ __forceinline__ float tanha(float x) {
    float y; asm("tanh.approx.f32 %0,%1;" : "=f"(y) : "f"(x)); return y;
}
__device__ __forceinline__ float siga(float x) { return fmaf(0.5f, tanha(0.5f * x), 0.5f); }
__device__ __forceinline__ u64 tanh2(u64 v) { float a, b; up2(v, a, b); return pk2(tanha(a), tanha(b)); }

// plain (schedulable) 128-bit shared loads: two packed f32x2 values
#define LDX2(x0, x1, ptr) do { \
    const ulonglong2 _v = *reinterpret_cast<const ulonglong2*>(ptr); \
    (x0) = _v.x; (x1) = _v.y; } while (0)

__device__ __forceinline__ void cpa16(float* dst, const float* src) {
    unsigned d = (unsigned)__cvta_generic_to_shared(dst);
    asm volatile("cp.async.cg.shared.global [%0], [%1], 16;" :: "r"(d), "l"(src));
}
#define CP_COMMIT() asm volatile("cp.async.commit_group;" ::: "memory")
#define CP_WAIT0()  asm volatile("cp.async.wait_group 0;" ::: "memory")

// stage matrix for phase ph into slot ph&1
// phases: 0..5 flow (Wr0,Wz0,Wh0,Wr1,Wz1,Wh1) [k][n] contiguous
//         6..8 Whh gates [n][k] pad 132 ; 9 Wih [n][k] pad 44
__device__ __forceinline__ void stage_matrix(int ph, float* sm, int tid,
    const float* fWr, const float* fWz, const float* fWh,
    const float* Whh, const float* Wih)
{
    float* dst = sm + (ph & 1) * SLOT;
    if (ph < 6) {
        const int l = ph / 3, w = ph % 3;
        const float* src = (w == 0 ? fWr : (w == 1 ? fWz : fWh)) + (size_t)l * 129 * 128;
        for (int i = tid; i < 4128; i += NTHR) cpa16(dst + i * 4, src + i * 4);
    } else if (ph < 9) {
        const float* src = Whh + (size_t)(ph - 6) * 128 * 128;
        for (int i = tid; i < 4096; i += NTHR) {
            int r = i >> 5, c = i & 31;
            cpa16(dst + r * 132 + c * 4, src + r * 128 + c * 4);
        }
    } else {
        for (int i = tid; i < 3840; i += NTHR) {
            int r = i / 10, c = i - r * 10;
            cpa16(dst + r * 44 + c * 4, Wih + r * 40 + c * 4);
        }
    }
}

// flow pass, split-K: weights [k][n], 4 cols n0..n0+3; pairs pg, pg+8;
// k range [kbase, kbase+64). acc[4i+c] = (pair_i, col n0+c) partial.
__device__ __forceinline__ void pass_flow_k(const float* sW, const float* xb,
                                            int n0, int kbase, u64 acc[8])
{
#pragma unroll 1
    for (int kk = 0; kk < 64; kk += 4) {
        const int k = kbase + kk;
        const float4 w0 = *(const float4*)&sW[(k+0)*128 + n0];
        const float4 w1 = *(const float4*)&sW[(k+1)*128 + n0];
        const float4 w2 = *(const float4*)&sW[(k+2)*128 + n0];
        const float4 w3 = *(const float4*)&sW[(k+3)*128 + n0];
#pragma unroll
        for (int i = 0; i < 2; i++) {
            u64 x0,x1,x2,x3;
            LDX2(x0,x1, xb + i*(8*HSTR) + k*2);
            LDX2(x2,x3, xb + i*(8*HSTR) + k*2 + 4);
            acc[4*i+0] = fma2(x0, pk2(w0.x,w0.x), acc[4*i+0]);
            acc[4*i+1] = fma2(x0, pk2(w0.y,w0.y), acc[4*i+1]);
            acc[4*i+2] = fma2(x0, pk2(w0.z,w0.z), acc[4*i+2]);
            acc[4*i+3] = fma2(x0, pk2(w0.w,w0.w), acc[4*i+3]);
            acc[4*i+0] = fma2(x1, pk2(w1.x,w1.x), acc[4*i+0]);
            acc[4*i+1] = fma2(x1, pk2(w1.y,w1.y), acc[4*i+1]);
            acc[4*i+2] = fma2(x1, pk2(w1.z,w1.z), acc[4*i+2]);
            acc[4*i+3] = fma2(x1, pk2(w1.w,w1.w), acc[4*i+3]);
            acc[4*i+0] = fma2(x2, pk2(w2.x,w2.x), acc[4*i+0]);
            acc[4*i+1] = fma2(x2, pk2(w2.y,w2.y), acc[4*i+1]);
            acc[4*i+2] = fma2(x2, pk2(w2.z,w2.z), acc[4*i+2]);
            acc[4*i+3] = fma2(x2, pk2(w2.w,w2.w), acc[4*i+3]);
            acc[4*i+0] = fma2(x3, pk2(w3.x,w3.x), acc[4*i+0]);
            acc[4*i+1] = fma2(x3, pk2(w3.y,w3.y), acc[4*i+1]);
            acc[4*i+2] = fma2(x3, pk2(w3.z,w3.z), acc[4*i+2]);
            acc[4*i+3] = fma2(x3, pk2(w3.w,w3.w), acc[4*i+3]);
        }
    }
}

// gh pass (full K, split-N): weights [n][k] pad 132, cols {n0s, n0s+64}; pairs pg, pg+8
__device__ __forceinline__ void pass_gh(const float* sW, const float* xb, int n0s, u64 acc[4])
{
#pragma unroll 2
    for (int k = 0; k < 128; k += 4) {
        const float4 wA = *(const float4*)&sW[n0s*132 + k];
        const float4 wB = *(const float4*)&sW[(n0s+64)*132 + k];
        const u64 a0 = pk2(wA.x,wA.x), a1 = pk2(wA.y,wA.y), a2 = pk2(wA.z,wA.z), a3 = pk2(wA.w,wA.w);
        const u64 b0 = pk2(wB.x,wB.x), b1 = pk2(wB.y,wB.y), b2 = pk2(wB.z,wB.z), b3 = pk2(wB.w,wB.w);
#pragma unroll
        for (int i = 0; i < 2; i++) {
            u64 x0,x1,x2,x3;
            LDX2(x0,x1, xb + i*(8*HSTR) + k*2);
            LDX2(x2,x3, xb + i*(8*HSTR) + k*2 + 4);
            acc[2*i+0] = fma2(x0,a0,acc[2*i+0]); acc[2*i+1] = fma2(x0,b0,acc[2*i+1]);
            acc[2*i+0] = fma2(x1,a1,acc[2*i+0]); acc[2*i+1] = fma2(x1,b1,acc[2*i+1]);
            acc[2*i+0] = fma2(x2,a2,acc[2*i+0]); acc[2*i+1] = fma2(x2,b2,acc[2*i+1]);
            acc[2*i+0] = fma2(x3,a3,acc[2*i+0]); acc[2*i+1] = fma2(x3,b3,acc[2*i+1]);
        }
    }
}

// gi pass (full K=40, split-N): weights [n][k] pad 44, cols {n0s, n0s+64}
__device__ __forceinline__ void pass_gi(const float* sW, const float* xb, int n0s, u64 acc[4])
{
#pragma unroll 2
    for (int k = 0; k < 40; k += 4) {
        const float4 wA = *(const float4*)&sW[n0s*44 + k];
        const float4 wB = *(const float4*)&sW[(n0s+64)*44 + k];
        const u64 a0 = pk2(wA.x,wA.x), a1 = pk2(wA.y,wA.y), a2 = pk2(wA.z,wA.z), a3 = pk2(wA.w,wA.w);
        const u64 b0 = pk2(wB.x,wB.x), b1 = pk2(wB.y,wB.y), b2 = pk2(wB.z,wB.z), b3 = pk2(wB.w,wB.w);
#pragma unroll
        for (int i = 0; i < 2; i++) {
            u64 x0,x1,x2,x3;
            LDX2(x0,x1, xb + i*(8*XSTR) + k*2);
            LDX2(x2,x3, xb + i*(8*XSTR) + k*2 + 4);
            acc[2*i+0] = fma2(x0,a0,acc[2*i+0]); acc[2*i+1] = fma2(x0,b0,acc[2*i+1]);
            acc[2*i+0] = fma2(x1,a1,acc[2*i+0]); acc[2*i+1] = fma2(x1,b1,acc[2*i+1]);
            acc[2*i+0] = fma2(x2,a2,acc[2*i+0]); acc[2*i+1] = fma2(x2,b2,acc[2*i+1]);
            acc[2*i+0] = fma2(x3,a3,acc[2*i+0]); acc[2*i+1] = fma2(x3,b3,acc[2*i+1]);
        }
    }
}

// split-K partial exchange: hi half stores, everyone syncs, lo half folds in
__device__ __forceinline__ void reduce_partials(float* sm, int tid, u64 acc[8])
{
    if (tid >= 256) {
        const int t2 = tid - 256;
#pragma unroll
        for (int q = 0; q < 8; q++)
            *(u64*)&sm[OFF_SCR + q * 512 + t2 * 2] = acc[q];
    }
    __syncthreads();
    if (tid < 256) {
#pragma unroll
        for (int q = 0; q < 8; q++)
            acc[q] = add2(acc[q], *(const u64*)&sm[OFF_SCR + q * 512 + tid * 2]);
    }
}

__global__ void __launch_bounds__(NTHR, 1)
odernn_persistent(const float* __restrict__ s,   const float* __restrict__ a,
                  const float* __restrict__ t,
                  const float* __restrict__ fWr, const float* __restrict__ fbr,
                  const float* __restrict__ fWz, const float* __restrict__ fbz,
                  const float* __restrict__ fWh, const float* __restrict__ fbh,
                  const float* __restrict__ ftw,
                  const float* __restrict__ Wih, const float* __restrict__ Whh,
                  const float* __restrict__ bih, const float* __restrict__ bhh,
                  const float* __restrict__ decW, const float* __restrict__ decb,
                  float* __restrict__ outs, float* __restrict__ hids)
{
    extern __shared__ float sm[];
    const int tid  = threadIdx.x;
    const int row0 = blockIdx.x * 32;

    const int w    = tid >> 5;           // warp 0..15
    const int lane = tid & 31;
    const int wl   = w & 7;              // warp-in-half 0..7
    const int kb   = (w >> 3) * 64;      // split-K base: 0 or 64
    const int pg   = lane >> 2;          // pair-group 0..7 (pairs pg, pg+8)
    const int cg   = lane & 3;           // col-group 0..3
    const int n0c  = wl * 16 + cg * 4;   // flow: 4 consecutive cols
    const int n0s  = w * 4 + cg;         // GRU: cols {n0s, n0s+64}, n0s in 0..63

    const float* htb = sm + OFF_HT + pg * HSTR;
    const float* rhb = sm + OFF_RH + pg * HSTR;
    const float* xtb = sm + OFF_XT + pg * XSTR;

    // ---- one-time init ----
    for (int i = tid; i < 16 * HSTR; i += NTHR) sm[OFF_HT + i] = 0.0f;
    if (tid < 128) {
#pragma unroll
        for (int l = 0; l < 2; l++) {
            sm[OFF_FB + l * 512 +   0 + tid] = fbr[l * HH + tid];
            sm[OFF_FB + l * 512 + 128 + tid] = fbz[l * HH + tid];
            sm[OFF_FB + l * 512 + 256 + tid] = fbh[l * HH + tid];
            sm[OFF_FB + l * 512 + 384 + tid] = ftw[l * HH + tid];
        }
    }
    if (tid < 384) { sm[OFF_BIH + tid] = bih[tid]; sm[OFF_BHH + tid] = bhh[tid]; }
    if (tid < 32) sm[OFF_DB + tid] = decb[tid];
    for (int i = tid; i < 1024; i += NTHR) {       // dec [d][k] pad 132
        int r = i >> 5, c = i & 31;
        cpa16(sm + OFF_DEC + r * 132 + c * 4, decW + r * 128 + c * 4);
    }
    stage_matrix(0, sm, tid, fWr, fWz, fWh, Whh, Wih);
    CP_COMMIT();

#pragma unroll 1
    for (int ti = 0; ti < T_STEPS; ti++) {
        if (tid < 32) sm[OFF_TV + tid] = t[(size_t)(row0 + tid) * T_STEPS + ti];
        for (int i = tid; i < 32 * 40; i += NTHR) {
            const int m = i / 40, c = i - m * 40;
            const size_t row = row0 + m;
            const float v = (c < DS) ? s[(row * T_STEPS + ti) * DS + c]
                                     : a[(row * T_STEPS + ti) * DA + (c - DS)];
            sm[OFF_XT + (m >> 1) * XSTR + 2 * c + (m & 1)] = v;
        }

        u64 zz[8], tvp[2];

        // =================== flow layers ===================
#pragma unroll 1
        for (int l = 0; l < 2; l++) {
            const int phb = l * 3;
            const float* bias = sm + OFF_FB + l * 512;

            // ---- pass r ----
            CP_WAIT0(); __syncthreads();
            stage_matrix(phb + 1, sm, tid, fWr, fWz, fWh, Whh, Wih); CP_COMMIT();
            {
                const float* sW = sm + (phb & 1) * SLOT;
                u64 acc[8];
#pragma unroll
                for (int q = 0; q < 8; q++) acc[q] = 0ULL;
                pass_flow_k(sW, htb, n0c, kb, acc);
                reduce_partials(sm, tid, acc);
                if (tid < 256) {
#pragma unroll
                    for (int i = 0; i < 2; i++) {
                        const int p = pg + 8 * i;
                        tvp[i] = pk2(sm[OFF_TV + 2 * p], sm[OFF_TV + 2 * p + 1]);
                    }
                    const float4 wt = *(const float4*)&sW[128 * 128 + n0c];
                    const float4 br = *(const float4*)&bias[n0c];
#pragma unroll
                    for (int i = 0; i < 2; i++) {
                        const int p = pg + 8 * i;
                        const ulonglong2 hA = *(const ulonglong2*)&sm[OFF_HT + p * HSTR + 2 * n0c];
                        const ulonglong2 hB = *(const ulonglong2*)&sm[OFF_HT + p * HSTR + 2 * n0c + 4];
                        float x, y;
                        ulonglong2 oA, oB;
                        up2(fma2(tvp[i], pk2(wt.x,wt.x), acc[4*i+0]), x, y);
                        oA.x = mul2(pk2(0.8f*siga(x+br.x), 0.8f*siga(y+br.x)), hA.x);
                        up2(fma2(tvp[i], pk2(wt.y,wt.y), acc[4*i+1]), x, y);
                        oA.y = mul2(pk2(0.8f*siga(x+br.y), 0.8f*siga(y+br.y)), hA.y);
                        up2(fma2(tvp[i], pk2(wt.z,wt.z), acc[4*i+2]), x, y);
                        oB.x = mul2(pk2(0.8f*siga(x+br.z), 0.8f*siga(y+br.z)), hB.x);
                        up2(fma2(tvp[i], pk2(wt.w,wt.w), acc[4*i+3]), x, y);
                        oB.y = mul2(pk2(0.8f*siga(x+br.w), 0.8f*siga(y+br.w)), hB.y);
                        *(ulonglong2*)&sm[OFF_RH + p * HSTR + 2 * n0c]     = oA;
                        *(ulonglong2*)&sm[OFF_RH + p * HSTR + 2 * n0c + 4] = oB;
                    }
                }
            }

            // ---- pass z ----
            CP_WAIT0(); __syncthreads();
            stage_matrix(phb + 2, sm, tid, fWr, fWz, fWh, Whh, Wih); CP_COMMIT();
            {
                const float* sW = sm + ((phb + 1) & 1) * SLOT;
                u64 acc[8];
#pragma unroll
                for (int q = 0; q < 8; q++) acc[q] = 0ULL;
                pass_flow_k(sW, htb, n0c, kb, acc);
                reduce_partials(sm, tid, acc);
                if (tid < 256) {
                    const float4 wt = *(const float4*)&sW[128 * 128 + n0c];
                    const float4 bz = *(const float4*)&bias[128 + n0c];
#pragma unroll
                    for (int i = 0; i < 2; i++) {
                        float x, y;
                        up2(fma2(tvp[i], pk2(wt.x,wt.x), acc[4*i+0]), x, y);
                        zz[4*i+0] = pk2(0.4f*siga(x+bz.x), 0.4f*siga(y+bz.x));
                        up2(fma2(tvp[i], pk2(wt.y,wt.y), acc[4*i+1]), x, y);
                        zz[4*i+1] = pk2(0.4f*siga(x+bz.y), 0.4f*siga(y+bz.y));
                        up2(fma2(tvp[i], pk2(wt.z,wt.z), acc[4*i+2]), x, y);
                        zz[4*i+2] = pk2(0.4f*siga(x+bz.z), 0.4f*siga(y+bz.z));
                        up2(fma2(tvp[i], pk2(wt.w,wt.w), acc[4*i+3]), x, y);
                        zz[4*i+3] = pk2(0.4f*siga(x+bz.w), 0.4f*siga(y+bz.w));
                    }
                }
            }

            // ---- pass u + combine ----
            CP_WAIT0(); __syncthreads();
            {
                stage_matrix(phb + 3, sm, tid, fWr, fWz, fWh, Whh, Wih); CP_COMMIT();
                const float* sW = sm + ((phb + 2) & 1) * SLOT;
                u64 acc[8];
#pragma unroll
                for (int q = 0; q < 8; q++) acc[q] = 0ULL;
                pass_flow_k(sW, rhb, n0c, kb, acc);
                reduce_partials(sm, tid, acc);
                if (tid < 256) {
                    const float4 wt = *(const float4*)&sW[128 * 128 + n0c];
                    const float4 bh = *(const float4*)&bias[256 + n0c];
                    const float4 tw = *(const float4*)&bias[384 + n0c];
#pragma unroll
                    for (int i = 0; i < 2; i++) {
                        const int p = pg + 8 * i;
                        const ulonglong2 hA = *(const ulonglong2*)&sm[OFF_HT + p * HSTR + 2 * n0c];
                        const ulonglong2 hB = *(const ulonglong2*)&sm[OFF_HT + p * HSTR + 2 * n0c + 4];
                        const u64 u0 = tanh2(add2(fma2(tvp[i], pk2(wt.x,wt.x), acc[4*i+0]), pk2(bh.x,bh.x)));
                        const u64 u1 = tanh2(add2(fma2(tvp[i], pk2(wt.y,wt.y), acc[4*i+1]), pk2(bh.y,bh.y)));
                        const u64 u2 = tanh2(add2(fma2(tvp[i], pk2(wt.z,wt.z), acc[4*i+2]), pk2(bh.z,bh.z)));
                        const u64 u3 = tanh2(add2(fma2(tvp[i], pk2(wt.w,wt.w), acc[4*i+3]), pk2(bh.w,bh.w)));
                        const u64 f0 = tanh2(mul2(pk2(tw.x,tw.x), tvp[i]));
                        const u64 f1 = tanh2(mul2(pk2(tw.y,tw.y), tvp[i]));
                        const u64 f2 = tanh2(mul2(pk2(tw.z,tw.z), tvp[i]));
                        const u64 f3 = tanh2(mul2(pk2(tw.w,tw.w), tvp[i]));
                        ulonglong2 oA, oB;
                        oA.x = fma2(mul2(f0, zz[4*i+0]), sub2(u0, hA.x), hA.x);
                        oA.y = fma2(mul2(f1, zz[4*i+1]), sub2(u1, hA.y), hA.y);
                        oB.x = fma2(mul2(f2, zz[4*i+2]), sub2(u2, hB.x), hB.x);
                        oB.y = fma2(mul2(f3, zz[4*i+3]), sub2(u3, hB.y), hB.y);
                        *(ulonglong2*)&sm[OFF_HT + p * HSTR + 2 * n0c]     = oA;
                        *(ulonglong2*)&sm[OFF_HT + p * HSTR + 2 * n0c + 4] = oB;
                        if (l == 1) {
                            float l0,h0,l1,h1,l2,h2,l3,h3;
                            up2(oA.x, l0, h0); up2(oA.y, l1, h1);
                            up2(oB.x, l2, h2); up2(oB.y, l3, h3);
                            const size_t rg = row0 + 2 * p;
                            *(float4*)&hids[(rg * T_STEPS + ti) * (size_t)HH + n0c]       = make_float4(l0, l1, l2, l3);
                            *(float4*)&hids[((rg + 1) * T_STEPS + ti) * (size_t)HH + n0c] = make_float4(h0, h1, h2, h3);
                        }
                    }
                }
            }
        }

        // =================== GRU (full-K split-N; all 16 warps) ===================
        u64 g_r[4], g_z[4], g_in[4], g_hn[4];
        {
            const float br0 = sm[OFF_BIH + n0s] + sm[OFF_BHH + n0s];
            const float br1 = sm[OFF_BIH + n0s + 64] + sm[OFF_BHH + n0s + 64];
            const float bz0 = sm[OFF_BIH + 128 + n0s] + sm[OFF_BHH + 128 + n0s];
            const float bz1 = sm[OFF_BIH + 128 + n0s + 64] + sm[OFF_BHH + 128 + n0s + 64];
            const float bi0 = sm[OFF_BIH + 256 + n0s],      bi1 = sm[OFF_BIH + 256 + n0s + 64];
            const float bn0 = sm[OFF_BHH + 256 + n0s],      bn1 = sm[OFF_BHH + 256 + n0s + 64];
#pragma unroll
            for (int i = 0; i < 2; i++) {
                g_r[2*i+0] = pk2(br0, br0); g_r[2*i+1] = pk2(br1, br1);
                g_z[2*i+0] = pk2(bz0, bz0); g_z[2*i+1] = pk2(bz1, bz1);
                g_in[2*i+0] = pk2(bi0, bi0); g_in[2*i+1] = pk2(bi1, bi1);
                g_hn[2*i+0] = pk2(bn0, bn0); g_hn[2*i+1] = pk2(bn1, bn1);
            }
        }
        // ghr (phase 6, slot 0)
        CP_WAIT0(); __syncthreads();
        stage_matrix(7, sm, tid, fWr, fWz, fWh, Whh, Wih); CP_COMMIT();
        pass_gh(sm + 0 * SLOT, htb, n0s, g_r);
        // ghz (phase 7, slot 1)
        CP_WAIT0(); __syncthreads();
        stage_matrix(8, sm, tid, fWr, fWz, fWh, Whh, Wih); CP_COMMIT();
        pass_gh(sm + 1 * SLOT, htb, n0s, g_z);
        // ghn (phase 8, slot 0)
        CP_WAIT0(); __syncthreads();
        stage_matrix(9, sm, tid, fWr, fWz, fWh, Whh, Wih); CP_COMMIT();
        pass_gh(sm + 0 * SLOT, htb, n0s, g_hn);
        // gi (phase 9, slot 1) + combine
        CP_WAIT0(); __syncthreads();
        stage_matrix(0, sm, tid, fWr, fWz, fWh, Whh, Wih); CP_COMMIT();   // next step Wr0
        {
            const float* sW = sm + 1 * SLOT;
            pass_gi(sW,            xtb, n0s, g_r);
            pass_gi(sW + 128 * 44, xtb, n0s, g_z);
            pass_gi(sW + 256 * 44, xtb, n0s, g_in);
#pragma unroll
            for (int i = 0; i < 2; i++) {
                const int p = pg + 8 * i;
#pragma unroll
                for (int c = 0; c < 2; c++) {
                    const int n = n0s + 64 * c;
                    float rx, ry, zx, zy;
                    up2(g_r[2*i+c], rx, ry); up2(g_z[2*i+c], zx, zy);
                    const u64 r2 = pk2(siga(rx), siga(ry));
                    const u64 z2 = pk2(siga(zx), siga(zy));
                    const u64 nn2 = tanh2(fma2(r2, g_hn[2*i+c], g_in[2*i+c]));
                    const u64 h2 = *(const u64*)&sm[OFF_HT + p * HSTR + 2 * n];
                    const u64 hn2 = fma2(z2, sub2(h2, nn2), nn2);
                    *(u64*)&sm[OFF_HT + p * HSTR + 2 * n] = hn2;
                }
            }
        }
        __syncthreads();   // h_new visible for decoder

        // =================== decoder (lo half only) ===================
        if (tid < 256) {
            const int d = tid & 31, grp = tid >> 5;   // 8 grps x 2 pairs
            const float db = sm[OFF_DB + d];
            u64 o0 = pk2(db, db), o1 = pk2(db, db);
            const float* xa0 = sm + OFF_HT + (2 * grp) * HSTR;
            const float* xa1 = xa0 + HSTR;
#pragma unroll 2
            for (int k = 0; k < 128; k += 4) {
                const float4 wv = *(const float4*)&sm[OFF_DEC + d * 132 + k];
                const u64 wa = pk2(wv.x, wv.x), wb = pk2(wv.y, wv.y);
                const u64 wc = pk2(wv.z, wv.z), wd = pk2(wv.w, wv.w);
                u64 x0, x1, x2, x3;
                LDX2(x0, x1, xa0 + k * 2);
                LDX2(x2, x3, xa0 + k * 2 + 4);
                o0 = fma2(x0, wa, o0); o0 = fma2(x1, wb, o0);
                o0 = fma2(x2, wc, o0); o0 = fma2(x3, wd, o0);
                LDX2(x0, x1, xa1 + k * 2);
                LDX2(x2, x3, xa1 + k * 2 + 4);
                o1 = fma2(x0, wa, o1); o1 = fma2(x1, wb, o1);
                o1 = fma2(x2, wc, o1); o1 = fma2(x3, wd, o1);
            }
            float v0, v1, v2, v3;
            up2(o0, v0, v1); up2(o1, v2, v3);
            const size_t r0g = row0 + 4 * grp;
            outs[((r0g + 0) * T_STEPS + ti) * (size_t)DS + d] = v0;
            outs[((r0g + 1) * T_STEPS + ti) * (size_t)DS + d] = v1;
            outs[((r0g + 2) * T_STEPS + ti) * (size_t)DS + d] = v2;
            outs[((r0g + 3) * T_STEPS + ti) * (size_t)DS + d] = v3;
        }
    }
}

extern "C" void kernel_launch(void* const* d_in, const int* in_sizes, int n_in,
                              void* d_out, int out_size)
{
    const float* s    = (const float*)d_in[0];
    const float* a    = (const float*)d_in[1];
    const float* t    = (const float*)d_in[2];
    const float* fWr  = (const float*)d_in[3];
    const float* fbr  = (const float*)d_in[4];
    const float* fWz  = (const float*)d_in[5];
    const float* fbz  = (const float*)d_in[6];
    const float* fWh  = (const float*)d_in[7];
    const float* fbh  = (const float*)d_in[8];
    const float* ftw  = (const float*)d_in[9];
    const float* Wih  = (const float*)d_in[10];
    const float* Whh  = (const float*)d_in[11];
    const float* bih  = (const float*)d_in[12];
    const float* bhh  = (const float*)d_in[13];
    const float* decW = (const float*)d_in[14];
    const float* decb = (const float*)d_in[15];

    float* outs = (float*)d_out;
    float* hids = outs + (size_t)4096 * T_STEPS * DS;

    const int SMEM = SMEM_FL * 4;
    cudaFuncSetAttribute(odernn_persistent, cudaFuncAttributeMaxDynamicSharedMemorySize, SMEM);
    odernn_persistent<<<128, NTHR, SMEM>>>(s, a, t, fWr, fbr, fWz, fbz, fWh, fbh, ftw,
                                           Wih, Whh, bih, bhh, decW, decb, outs, hids);
}